// round 10
// baseline (speedup 1.0000x reference)
#include <cuda_runtime.h>
#include <cuda_fp16.h>
#include <cstdint>

#define NNODES_MAX 100000
#define EDGES_MAX  1600000
#define DH 128
#define NGRAPH 512

// ---------------- scratch (static device globals; no allocation) ------------
__device__ __half g_x16[NNODES_MAX * DH];    // input features, fp16
__device__ __half g_h16[NNODES_MAX * DH];    // layer output h, fp16
__device__ __half g_agg16[NNODES_MAX * DH];  // h + A*h, fp16
__device__ __half g_w16[3 * DH * DH];        // W0,W1,W2 in fp16
__device__ float  g_pool[NGRAPH * DH];       // per-graph sums (fp32)
__device__ float  g_cnt[NGRAPH];             // per-graph node counts
__device__ int    g_deg[NNODES_MAX];
__device__ int    g_cur[NNODES_MAX];
__device__ int    g_rowptr[NNODES_MAX + 1];
__device__ int    g_col[EDGES_MAX];

// ---------------- helpers ---------------------------------------------------
__device__ __forceinline__ void red2(float* p, float a, float b) {
    asm volatile("red.global.add.v2.f32 [%0], {%1,%2};"
                 :: "l"(p), "f"(a), "f"(b) : "memory");
}

// ---------------- init: zero pool/cnt/deg ------------------------------------
__global__ void init_kernel(int n) {
    int i = blockIdx.x * blockDim.x + threadIdx.x;
    if (i < NGRAPH * DH) g_pool[i] = 0.f;
    if (i < NGRAPH) g_cnt[i] = 0.f;
    if (i < n) g_deg[i] = 0;
}

// fused: degree histogram (over E) + per-graph node counts (over N)
__global__ void hist_count_kernel(const int* __restrict__ ei,
                                  const int* __restrict__ batch, int E, int N) {
    int i = blockIdx.x * blockDim.x + threadIdx.x;
    if (i < E) atomicAdd(&g_deg[ei[E + i]], 1);   // dst
    if (i < N) atomicAdd(&g_cnt[batch[i]], 1.0f);
}

// single-block exclusive scan of g_deg into g_rowptr; also seeds g_cur
__global__ void scan_kernel(int n) {
    const int T = 1024;
    __shared__ int part[T];
    int t = threadIdx.x;
    int C = (n + T - 1) / T;
    int beg = t * C;
    int end = beg + C < n ? beg + C : n;
    int s = 0;
    for (int i = beg; i < end; i++) s += g_deg[i];
    part[t] = s;
    __syncthreads();
    for (int off = 1; off < T; off <<= 1) {
        int v = (t >= off) ? part[t - off] : 0;
        __syncthreads();
        part[t] += v;
        __syncthreads();
    }
    int run = (t == 0) ? 0 : part[t - 1];
    for (int i = beg; i < end; i++) {
        g_rowptr[i] = run;
        g_cur[i]    = run;
        run += g_deg[i];
    }
    if (t == 0) g_rowptr[n] = part[T - 1];
}

__global__ void fill_kernel(const int* __restrict__ ei, int E) {
    int i = blockIdx.x * blockDim.x + threadIdx.x;
    if (i >= E) return;
    int s = ei[i];
    int d = ei[E + i];
    int pos = atomicAdd(&g_cur[d], 1);
    g_col[pos] = s;
}

// ---------------- converters -------------------------------------------------
__global__ void convert_x_kernel(const float4* __restrict__ x, int n4) {
    int i = blockIdx.x * blockDim.x + threadIdx.x;
    if (i >= n4) return;
    float4 v = x[i];
    __half2* dst = reinterpret_cast<__half2*>(g_x16);
    dst[i * 2]     = __floats2half2_rn(v.x, v.y);
    dst[i * 2 + 1] = __floats2half2_rn(v.z, v.w);
}

__global__ void convert_w_kernel(const float4* __restrict__ w, int layer) {
    int i = blockIdx.x * blockDim.x + threadIdx.x;
    const int n4 = DH * DH / 4;   // 4096
    if (i >= n4) return;
    float4 v = w[i];
    __half2* dst = reinterpret_cast<__half2*>(&g_w16[layer * DH * DH]);
    dst[i * 2]     = __floats2half2_rn(v.x, v.y);
    dst[i * 2 + 1] = __floats2half2_rn(v.z, v.w);
}

// ---------------- tensor-core gather: agg = self + Ind x Feats ----------------
// warp owns 16 dst nodes; chunks of 16 CSR edges; D[16dst x 128feat] fp32 accum.
// Ind[i][s] = 1.0h iff edge slot s belongs to dst i (from rowptr compares).
__global__ __launch_bounds__(256)
void gather_tc_kernel(const __half* __restrict__ srcp, int N) {
    __shared__ __align__(16) __half Sf[8][16][136];   // [warp][slot][feat], 272B rows
    __shared__ __align__(16) __half Ind[8][16][24];   // [warp][dst][slot], 48B rows

    const int wid  = threadIdx.x >> 5;
    const int lane = threadIdx.x & 31;
    const int d0 = (blockIdx.x * 8 + wid) * 16;
    if (d0 >= N) return;
    const int g = lane >> 2;          // 0..7
    const int c = (lane & 3) * 2;     // 0,2,4,6

    // rowptr window: lanes 0..16 hold rowptr[d0+lane] (clamped)
    int rp_idx = d0 + (lane < 16 ? lane : 16);
    if (rp_idx > N) rp_idx = N;
    int rp_l = g_rowptr[rp_idx];
    const int rp_i  = __shfl_sync(0xffffffffu, rp_l, lane >> 1);
    const int rp_i1 = __shfl_sync(0xffffffffu, rp_l, (lane >> 1) + 1);
    const int e0 = __shfl_sync(0xffffffffu, rp_l, 0);
    const int e1 = __shfl_sync(0xffffffffu, rp_l, 16);

    float acc[16][4];
#pragma unroll
    for (int f = 0; f < 16; f++)
#pragma unroll
        for (int q = 0; q < 4; q++) acc[f][q] = 0.f;

    const uint32_t sf_base  = (uint32_t)__cvta_generic_to_shared(&Sf[wid][0][0]);
    const uint32_t ind_base = (uint32_t)__cvta_generic_to_shared(&Ind[wid][0][0]);

    for (int cb = e0; cb < e1; cb += 16) {
        __syncwarp();   // prior chunk's ldmatrix reads done before overwrite
        // src node ids for the 16 slots (lanes 0..15)
        int s_l = 0;
        if (lane < 16 && cb + lane < e1) s_l = g_col[cb + lane];
        // stage 16 rows x 256B via cp.async (8 x 16B per lane)
#pragma unroll
        for (int t = 0; t < 8; t++) {
            int slot = 2 * t + (lane >> 4);
            int srow = __shfl_sync(0xffffffffu, s_l, slot);
            uint32_t daddr = sf_base + slot * 272 + (lane & 15) * 16;
            const __half* gp = srcp + srow * DH + (lane & 15) * 8;
            asm volatile("cp.async.cg.shared.global [%0], [%1], 16;"
                         :: "r"(daddr), "l"(gp) : "memory");
        }
        asm volatile("cp.async.commit_group;" ::: "memory");
        // indicator tile: lane covers dst row i=lane>>1, slots (lane&1)*8..+8
        {
            int i = lane >> 1;
            int bs = (lane & 1) * 8;
            uint32_t w0, w1, w2, w3;
            {
                int p0 = cb + bs;
                uint32_t h0 = (p0+0 >= rp_i && p0+0 < rp_i1) ? 0x3C00u : 0u;
                uint32_t h1 = (p0+1 >= rp_i && p0+1 < rp_i1) ? 0x3C00u : 0u;
                uint32_t h2 = (p0+2 >= rp_i && p0+2 < rp_i1) ? 0x3C00u : 0u;
                uint32_t h3 = (p0+3 >= rp_i && p0+3 < rp_i1) ? 0x3C00u : 0u;
                uint32_t h4 = (p0+4 >= rp_i && p0+4 < rp_i1) ? 0x3C00u : 0u;
                uint32_t h5 = (p0+5 >= rp_i && p0+5 < rp_i1) ? 0x3C00u : 0u;
                uint32_t h6 = (p0+6 >= rp_i && p0+6 < rp_i1) ? 0x3C00u : 0u;
                uint32_t h7 = (p0+7 >= rp_i && p0+7 < rp_i1) ? 0x3C00u : 0u;
                w0 = h0 | (h1 << 16); w1 = h2 | (h3 << 16);
                w2 = h4 | (h5 << 16); w3 = h6 | (h7 << 16);
            }
            uint32_t ia = ind_base + i * 48 + (lane & 1) * 16;
            asm volatile("st.shared.v4.b32 [%0], {%1,%2,%3,%4};"
                         :: "r"(ia), "r"(w0), "r"(w1), "r"(w2), "r"(w3) : "memory");
        }
        asm volatile("cp.async.wait_group 0;" ::: "memory");
        __syncwarp();
        // A frag: indicator 16x16, row-major, non-trans x4
        uint32_t a0, a1, a2, a3;
        {
            uint32_t aaddr = ind_base + (lane & 15) * 48 + (lane >> 4) * 16;
            asm volatile("ldmatrix.sync.aligned.m8n8.x4.shared.b16 {%0,%1,%2,%3}, [%4];"
                         : "=r"(a0), "=r"(a1), "=r"(a2), "=r"(a3) : "r"(aaddr));
        }
        // B frags (trans from [slot][feat]) + mma, two feat tiles per ldmatrix
#pragma unroll
        for (int f = 0; f < 16; f += 2) {
            uint32_t b0, b1, b2, b3;
            uint32_t baddr = sf_base + (lane & 15) * 272 + (f + (lane >> 4)) * 16;
            asm volatile("ldmatrix.sync.aligned.m8n8.x4.trans.shared.b16 {%0,%1,%2,%3}, [%4];"
                         : "=r"(b0), "=r"(b1), "=r"(b2), "=r"(b3) : "r"(baddr));
            asm volatile(
                "mma.sync.aligned.m16n8k16.row.col.f32.f16.f16.f32 "
                "{%0,%1,%2,%3}, {%4,%5,%6,%7}, {%8,%9}, {%0,%1,%2,%3};"
                : "+f"(acc[f][0]), "+f"(acc[f][1]), "+f"(acc[f][2]), "+f"(acc[f][3])
                : "r"(a0), "r"(a1), "r"(a2), "r"(a3), "r"(b0), "r"(b1));
            asm volatile(
                "mma.sync.aligned.m16n8k16.row.col.f32.f16.f16.f32 "
                "{%0,%1,%2,%3}, {%4,%5,%6,%7}, {%8,%9}, {%0,%1,%2,%3};"
                : "+f"(acc[f+1][0]), "+f"(acc[f+1][1]), "+f"(acc[f+1][2]), "+f"(acc[f+1][3])
                : "r"(a0), "r"(a1), "r"(a2), "r"(a3), "r"(b2), "r"(b3));
        }
    }

    // epilogue: add own features, store agg16
#pragma unroll
    for (int hf = 0; hf < 2; hf++) {
        int dst = d0 + g + hf * 8;
        if (dst < N) {
#pragma unroll
            for (int f = 0; f < 16; f++) {
                float2 own = __half22float2(
                    *reinterpret_cast<const __half2*>(&srcp[dst * DH + f * 8 + c]));
                float o0 = acc[f][hf * 2 + 0] + own.x;
                float o1 = acc[f][hf * 2 + 1] + own.y;
                *reinterpret_cast<__half2*>(&g_agg16[dst * DH + f * 8 + c]) =
                    __floats2half2_rn(o0, o1);
            }
        }
    }
}

// ---------------- tensor-core GEMM: C = act( agg16 @ W^T + b ) ---------------
// mma.sync m16n8k16 f16*f16+f32. BM=128, BN=128, BK=64 (2 stages), 8 warps.
template<bool RELU, bool POOL>
__global__ __launch_bounds__(256)
void hgemm_kernel(const __half* __restrict__ Wh, const float* __restrict__ bias,
                  const int* __restrict__ batch, int M) {
    __shared__ __half As[128 * 72];   // [m][k], stride 72 (pad 8)
    __shared__ __half Ws[128 * 72];   // [n][k]

    const int tid  = threadIdx.x;
    const int wid  = tid >> 5;
    const int lane = tid & 31;
    const int g    = lane >> 2;
    const int c    = (lane & 3) * 2;
    const int mrow = (wid & 1) * 64;
    const int ncol = (wid >> 1) * 32;
    const int rowBase = blockIdx.x * 128;

    float acc[4][4][4];
#pragma unroll
    for (int mt = 0; mt < 4; mt++)
#pragma unroll
        for (int nt = 0; nt < 4; nt++)
#pragma unroll
            for (int q = 0; q < 4; q++) acc[mt][nt][q] = 0.f;

#pragma unroll
    for (int kc = 0; kc < DH; kc += 64) {
        __syncthreads();
#pragma unroll
        for (int t = 0; t < 4; t++) {
            int idx = tid + t * 256;
            int row = idx >> 3;
            int ch  = (idx & 7) * 8;
            int grow = rowBase + row;
            if (grow >= M) grow = M - 1;
            *reinterpret_cast<uint4*>(&As[row * 72 + ch]) =
                *reinterpret_cast<const uint4*>(&g_agg16[grow * DH + kc + ch]);
            *reinterpret_cast<uint4*>(&Ws[row * 72 + ch]) =
                *reinterpret_cast<const uint4*>(&Wh[row * DH + kc + ch]);
        }
        __syncthreads();

#pragma unroll
        for (int kk = 0; kk < 4; kk++) {
            const int k0 = kk * 16;
            uint32_t af[4][4], bf[4][2];
#pragma unroll
            for (int mt = 0; mt < 4; mt++) {
                uint32_t aaddr = (uint32_t)__cvta_generic_to_shared(
                    &As[(mrow + mt * 16 + (lane & 15)) * 72 + k0 + ((lane >> 4) << 3)]);
                asm volatile(
                    "ldmatrix.sync.aligned.m8n8.x4.shared.b16 {%0,%1,%2,%3}, [%4];"
                    : "=r"(af[mt][0]), "=r"(af[mt][1]),
                      "=r"(af[mt][2]), "=r"(af[mt][3])
                    : "r"(aaddr));
            }
#pragma unroll
            for (int nt = 0; nt < 4; nt++) {
                uint32_t baddr = (uint32_t)__cvta_generic_to_shared(
                    &Ws[(ncol + nt * 8 + (lane & 7)) * 72 + k0 + (((lane >> 3) & 1) << 3)]);
                asm volatile(
                    "ldmatrix.sync.aligned.m8n8.x2.shared.b16 {%0,%1}, [%2];"
                    : "=r"(bf[nt][0]), "=r"(bf[nt][1])
                    : "r"(baddr));
            }
#pragma unroll
            for (int mt = 0; mt < 4; mt++)
#pragma unroll
                for (int nt = 0; nt < 4; nt++) {
                    asm volatile(
                        "mma.sync.aligned.m16n8k16.row.col.f32.f16.f16.f32 "
                        "{%0,%1,%2,%3}, {%4,%5,%6,%7}, {%8,%9}, {%0,%1,%2,%3};"
                        : "+f"(acc[mt][nt][0]), "+f"(acc[mt][nt][1]),
                          "+f"(acc[mt][nt][2]), "+f"(acc[mt][nt][3])
                        : "r"(af[mt][0]), "r"(af[mt][1]), "r"(af[mt][2]), "r"(af[mt][3]),
                          "r"(bf[nt][0]), "r"(bf[nt][1]));
                }
        }
    }

    // epilogue
#pragma unroll
    for (int nt = 0; nt < 4; nt++) {
        int col = ncol + nt * 8 + c;
        float2 bb = *reinterpret_cast<const float2*>(&bias[col]);
#pragma unroll
        for (int mt = 0; mt < 4; mt++) {
            int row0 = rowBase + mrow + mt * 16 + g;
            int row1 = row0 + 8;
            float c0 = acc[mt][nt][0] + bb.x;
            float c1 = acc[mt][nt][1] + bb.y;
            float c2 = acc[mt][nt][2] + bb.x;
            float c3 = acc[mt][nt][3] + bb.y;
            if (RELU) {
                c0 = fmaxf(c0, 0.f); c1 = fmaxf(c1, 0.f);
                c2 = fmaxf(c2, 0.f); c3 = fmaxf(c3, 0.f);
            }
            if (POOL) {
                if (row0 < M) red2(&g_pool[batch[row0] * DH + col], c0, c1);
                if (row1 < M) red2(&g_pool[batch[row1] * DH + col], c2, c3);
            } else {
                if (row0 < M)
                    *reinterpret_cast<__half2*>(&g_h16[row0 * DH + col]) =
                        __floats2half2_rn(c0, c1);
                if (row1 < M)
                    *reinterpret_cast<__half2*>(&g_h16[row1 * DH + col]) =
                        __floats2half2_rn(c2, c3);
            }
        }
    }
}

// ---------------- head: out[g][o] = dot(pool[g]/cnt[g], Wg[o]) + bg[o] ------
__global__ void final_kernel(const float* __restrict__ Wg,
                             const float* __restrict__ bg,
                             float* __restrict__ out) {
    int g = blockIdx.x;
    int lane = threadIdx.x;
    float4 p = reinterpret_cast<const float4*>(g_pool)[g * 32 + lane];
    float c = fmaxf(g_cnt[g], 1.0f);
#pragma unroll
    for (int o = 0; o < 10; o++) {
        float4 w = reinterpret_cast<const float4*>(Wg)[o * 32 + lane];
        float s = p.x * w.x + p.y * w.y + p.z * w.z + p.w * w.w;
#pragma unroll
        for (int off = 16; off; off >>= 1) s += __shfl_xor_sync(0xffffffffu, s, off);
        if (lane == 0) out[g * 10 + o] = s / c + bg[o];
    }
}

// ---------------- launch ----------------------------------------------------
extern "C" void kernel_launch(void* const* d_in, const int* in_sizes, int n_in,
                              void* d_out, int out_size) {
    const float* x     = (const float*)d_in[0];
    const int*   ei    = (const int*)d_in[1];      // int32 (JAX x64 disabled)
    const int*   batch = (const int*)d_in[2];
    const float* W0 = (const float*)d_in[3];
    const float* b0 = (const float*)d_in[4];
    const float* W1 = (const float*)d_in[5];
    const float* b1 = (const float*)d_in[6];
    const float* W2 = (const float*)d_in[7];
    const float* b2 = (const float*)d_in[8];
    const float* Wg = (const float*)d_in[9];
    const float* bg = (const float*)d_in[10];
    float* out = (float*)d_out;

    const int N = in_sizes[0] / DH;     // 100000
    const int E = in_sizes[1] / 2;      // 1600000

    const int gemm_grid = (N + 127) / 128;
    const int gat_grid  = (N + 127) / 128;   // 8 warps x 16 dst nodes per block
    const int n4 = N * (DH / 4);

    __half* w16;
    cudaGetSymbolAddress((void**)&w16, g_w16);

    // CSR build + init + fp16 conversions
    init_kernel<<<(NGRAPH * DH > N ? NGRAPH * DH : N) / 512 + 1, 512>>>(N);
    hist_count_kernel<<<(E + 511) / 512, 512>>>(ei, batch, E, N);
    scan_kernel<<<1, 1024>>>(N);
    fill_kernel<<<(E + 511) / 512, 512>>>(ei, E);
    convert_x_kernel<<<(n4 + 511) / 512, 512>>>(reinterpret_cast<const float4*>(x), n4);
    convert_w_kernel<<<8, 512>>>(reinterpret_cast<const float4*>(W0), 0);
    convert_w_kernel<<<8, 512>>>(reinterpret_cast<const float4*>(W1), 1);
    convert_w_kernel<<<8, 512>>>(reinterpret_cast<const float4*>(W2), 2);

    __half* x16;  cudaGetSymbolAddress((void**)&x16, g_x16);
    __half* h16;  cudaGetSymbolAddress((void**)&h16, g_h16);

    // layer 0
    gather_tc_kernel<<<gat_grid, 256>>>(x16, N);
    hgemm_kernel<true, false><<<gemm_grid, 256>>>(w16, b0, nullptr, N);
    // layer 1
    gather_tc_kernel<<<gat_grid, 256>>>(h16, N);
    hgemm_kernel<true, false><<<gemm_grid, 256>>>(w16 + DH * DH, b1, nullptr, N);
    // layer 2 + fused pooling
    gather_tc_kernel<<<gat_grid, 256>>>(h16, N);
    hgemm_kernel<false, true><<<gemm_grid, 256>>>(w16 + 2 * DH * DH, b2, batch, N);

    final_kernel<<<NGRAPH, 32>>>(Wg, bg, out);
}